// round 12
// baseline (speedup 1.0000x reference)
#include <cuda_runtime.h>
#include <cuda_fp16.h>
#include <cuda.h>
#include <cstdint>
#include <cstddef>

// ---------------- problem dims ----------------
#define MB_   4096
#define DIN_  4096
#define HID_  16384
#define ONN_  1000
#define K2_   (DIN_ + HID_)

#define KC 64                   // fp16 K per stage (128 B rows = SW128 atom)
#define STAGE0_OFF 1024
#define KSPLIT 4
#define KSEG   (K2_ / KSPLIT)   // 5120

// fp16 scratch (static device arrays — no allocation)
__device__ __align__(1024) __half g_xf [(size_t)MB_ * DIN_];
__device__ __align__(1024) __half g_w1f[(size_t)HID_ * DIN_];
__device__ __align__(1024) __half g_w2f[(size_t)ONN_ * K2_];
__device__ __align__(1024) __half g_h1 [(size_t)MB_ * HID_];
__device__ __align__(1024) float  g_p2 [(size_t)KSPLIT * MB_ * 1024];
__device__ int g_cnt[256];      // per-(m-tile, n-tile) arrival counters

// ---------------- PTX helpers ------------------
__device__ __forceinline__ uint32_t smem_u32(const void* p) {
    uint32_t a;
    asm("{ .reg .u64 t; cvta.to.shared.u64 t, %1; cvt.u32.u64 %0, t; }"
        : "=r"(a) : "l"(p));
    return a;
}

#define MBARRIER_INIT(addr, cnt) \
    asm volatile("mbarrier.init.shared.b64 [%0], %1;" :: "r"(addr), "r"(cnt) : "memory")

#define MBARRIER_EXPECT_TX(addr, bytes) \
    asm volatile("mbarrier.arrive.expect_tx.shared.b64 _, [%0], %1;" \
                 :: "r"(addr), "r"(bytes) : "memory")

#define MBARRIER_ARRIVE(addr) \
    asm volatile("mbarrier.arrive.shared.b64 _, [%0];" :: "r"(addr) : "memory")

#define MBARRIER_WAIT_PARITY(addr, parity) do {                                   \
    uint32_t _m = (addr); uint32_t _p = (parity); uint32_t _d;                    \
    asm volatile("{ .reg .pred p; mbarrier.try_wait.parity.acquire.cta.shared::cta.b64 p, [%1], %2; selp.b32 %0, 1, 0, p; }" \
        : "=r"(_d) : "r"(_m), "r"(_p) : "memory");                                \
    if (!_d) {                                                                    \
        asm volatile("{ .reg .pred P1; WL_%=: mbarrier.try_wait.parity.acquire.cta.shared::cta.b64 P1, [%0], %1, 0x989680; @P1 bra.uni WD_%=; bra.uni WL_%=; WD_%=: }" \
            :: "r"(_m), "r"(_p) : "memory");                                      \
    }                                                                             \
} while (0)

__device__ __forceinline__ void tma2d(uint32_t dst, const CUtensorMap* m,
                                      int cx, int cy, uint32_t mbar) {
    asm volatile(
        "cp.async.bulk.tensor.2d.shared::cta.global.tile.mbarrier::complete_tx::bytes "
        "[%0], [%1, {%2, %3}], [%4];"
        :: "r"(dst), "l"(m), "r"(cx), "r"(cy), "r"(mbar) : "memory");
}

#define FENCE_PROXY_ASYNC() asm volatile("fence.proxy.async.shared::cta;" ::: "memory")

__device__ __forceinline__ void ldsm4(uint32_t* r, uint32_t addr) {
    asm volatile("ldmatrix.sync.aligned.m8n8.x4.shared.b16 {%0,%1,%2,%3}, [%4];"
                 : "=r"(r[0]), "=r"(r[1]), "=r"(r[2]), "=r"(r[3]) : "r"(addr));
}

__device__ __forceinline__ void mma16816(float* c, const uint32_t* a, uint32_t b0, uint32_t b1) {
    asm volatile(
        "mma.sync.aligned.m16n8k16.row.col.f32.f16.f16.f32 "
        "{%0,%1,%2,%3}, {%4,%5,%6,%7}, {%8,%9}, {%0,%1,%2,%3};"
        : "+f"(c[0]), "+f"(c[1]), "+f"(c[2]), "+f"(c[3])
        : "r"(a[0]), "r"(a[1]), "r"(a[2]), "r"(a[3]), "r"(b0), "r"(b1));
}

// ---------------- merged conversion (x, W1, W2 in one launch) --------------
#define N4X  ((size_t)MB_  * DIN_ / 4)
#define N4W1 ((size_t)HID_ * DIN_ / 4)
#define N4W2 ((size_t)ONN_ * K2_  / 4)

__global__ void conv_all(const float* __restrict__ x,
                         const float* __restrict__ w1,
                         const float* __restrict__ w2)
{
    size_t i = (size_t)blockIdx.x * blockDim.x + threadIdx.x;
    const float* src;
    __half* dst;
    if (i < N4X)               { src = x;  dst = g_xf;  }
    else if (i < N4X + N4W1)   { src = w1; dst = g_w1f; i -= N4X; }
    else if (i < N4X + N4W1 + N4W2) { src = w2; dst = g_w2f; i -= N4X + N4W1; }
    else return;

    float4 v = reinterpret_cast<const float4*>(src)[i];
    __half h0 = __float2half_rn(v.x);
    __half h1 = __float2half_rn(v.y);
    __half h2 = __float2half_rn(v.z);
    __half h3 = __float2half_rn(v.w);
    uint2 p;
    p.x = (uint32_t)__half_as_ushort(h0) | ((uint32_t)__half_as_ushort(h1) << 16);
    p.y = (uint32_t)__half_as_ushort(h2) | ((uint32_t)__half_as_ushort(h3) << 16);
    reinterpret_cast<uint2*>(dst)[i] = p;
}

// mainloop body with register fragment double-buffering (4 k16 slices/stage)
#define STAGE_MMAS(aB, bB)                                                        \
    do {                                                                          \
        uint32_t aa[2][4][4], bb[2][4][4];                                        \
        _Pragma("unroll")                                                         \
        for (int mi = 0; mi < 4; mi++)                                            \
            ldsm4(aa[0][mi], (aB) + (uint32_t)mi * 2048u + cb[0]);                \
        _Pragma("unroll")                                                         \
        for (int nj = 0; nj < 4; nj++)                                            \
            ldsm4(bb[0][nj], (bB) + (uint32_t)nj * 2048u + cb[0]);                \
        _Pragma("unroll")                                                         \
        for (int ks = 0; ks < 4; ks++) {                                          \
            const int cur = ks & 1, nxt = cur ^ 1;                                \
            if (ks < 3) {                                                         \
                _Pragma("unroll")                                                 \
                for (int mi = 0; mi < 4; mi++)                                    \
                    ldsm4(aa[nxt][mi], (aB) + (uint32_t)mi * 2048u + cb[ks + 1]); \
                _Pragma("unroll")                                                 \
                for (int nj = 0; nj < 4; nj++)                                    \
                    ldsm4(bb[nxt][nj], (bB) + (uint32_t)nj * 2048u + cb[ks + 1]); \
            }                                                                     \
            _Pragma("unroll")                                                     \
            for (int mi = 0; mi < 4; mi++)                                        \
                _Pragma("unroll")                                                 \
                for (int ni = 0; ni < 8; ni++) {                                  \
                    const uint32_t b0 = bb[cur][ni >> 1][ni & 1];                 \
                    const uint32_t b1 = bb[cur][ni >> 1][(ni & 1) + 2];           \
                    mma16816(acc[mi][ni], aa[cur][mi], b0, b1);                   \
                }                                                                 \
        }                                                                         \
    } while (0)

// ======================= GEMM1: BM=128 x BN=256, warp tile 64x64 =============
// h1 = relu(x_f16 @ W1_f16^T + b1) -> fp16, single pass   [unchanged winner]
__global__ __launch_bounds__(256, 1)
void gemm1_hmma(const __grid_constant__ CUtensorMap a_m,
                const __grid_constant__ CUtensorMap b_m,
                const float* __restrict__ bias)
{
    constexpr int NST = 2;
    constexpr uint32_t STG_A = 0;
    constexpr uint32_t STG_B = 16384;
    constexpr uint32_t STAGE_SZ = 49152;

    extern __shared__ __align__(1024) char smem[];
    const uint32_t sbase = smem_u32(smem);

    const int tid  = threadIdx.x;
    const int lane = tid & 31;
    const int wid  = tid >> 5;
    const int wm   = (wid & 1) * 64;
    const int wn   = (wid >> 1) * 64;

    if (tid == 0) {
        #pragma unroll
        for (int s = 0; s < NST; s++) {
            MBARRIER_INIT(sbase + 8u * s, 1);
            MBARRIER_INIT(sbase + 64u + 8u * s, 8);
        }
        FENCE_PROXY_ASYNC();
    }
    __syncthreads();

    const int m0 = blockIdx.x * 128;
    const int n0 = blockIdx.y * 256;
    const int T  = DIN_ / KC;

    const uint32_t rowoff = (uint32_t)(lane & 15) * 128u;
    const uint32_t hi4 = (uint32_t)(lane >> 4);
    const uint32_t lo7 = (uint32_t)(lane & 7);
    uint32_t cb[4];
    #pragma unroll
    for (int ks = 0; ks < 4; ks++)
        cb[ks] = (((2u * ks + hi4) ^ lo7) << 4);

    float acc[4][8][4];
    #pragma unroll
    for (int mi = 0; mi < 4; mi++)
        #pragma unroll
        for (int ni = 0; ni < 8; ni++)
            #pragma unroll
            for (int q = 0; q < 4; q++) acc[mi][ni][q] = 0.f;

    if (tid == 0) {
        #pragma unroll
        for (int j = 0; j < NST; j++) {
            const uint32_t full = sbase + 8u * j;
            MBARRIER_EXPECT_TX(full, STAGE_SZ);
            const uint32_t sb = sbase + STAGE0_OFF + (uint32_t)j * STAGE_SZ;
            tma2d(sb + STG_A, &a_m, j * KC, m0, full);
            tma2d(sb + STG_B, &b_m, j * KC, n0, full);
        }
    }

    int s = 0, ph = 0;
    #pragma unroll 1
    for (int i = 0; i < T; i++) {
        MBARRIER_WAIT_PARITY(sbase + 8u * s, (uint32_t)ph);

        const uint32_t sb = sbase + STAGE0_OFF + (uint32_t)s * STAGE_SZ;
        const uint32_t aB = sb + STG_A + (uint32_t)wm * 128u + rowoff;
        const uint32_t bB = sb + STG_B + (uint32_t)wn * 128u + rowoff;

        STAGE_MMAS(aB, bB);

        if (lane == 0) MBARRIER_ARRIVE(sbase + 64u + 8u * s);

        const int j = i + NST;
        if (tid == 0 && j < T) {
            MBARRIER_WAIT_PARITY(sbase + 64u + 8u * s, (uint32_t)ph);
            const uint32_t full = sbase + 8u * s;
            MBARRIER_EXPECT_TX(full, STAGE_SZ);
            tma2d(sb + STG_A, &a_m, j * KC, m0, full);
            tma2d(sb + STG_B, &b_m, j * KC, n0, full);
        }
        if (++s == NST) { s = 0; ph ^= 1; }
    }

    const int mrow = m0 + wm + (lane >> 2);
    const int ncol = n0 + wn + 2 * (lane & 3);

    #pragma unroll
    for (int mi = 0; mi < 4; mi++) {
        #pragma unroll
        for (int ni = 0; ni < 8; ni++) {
            const int n = ncol + ni * 8;
            const int ma = mrow + mi * 16;
            const int mb = ma + 8;
            const float2 bv = __ldg(reinterpret_cast<const float2*>(bias + n));
            float v00 = acc[mi][ni][0] + bv.x;
            float v01 = acc[mi][ni][1] + bv.y;
            float v10 = acc[mi][ni][2] + bv.x;
            float v11 = acc[mi][ni][3] + bv.y;
            v00 = v00 > 0.f ? v00 : 0.f;
            v01 = v01 > 0.f ? v01 : 0.f;
            v10 = v10 > 0.f ? v10 : 0.f;
            v11 = v11 > 0.f ? v11 : 0.f;
            uint32_t p0 = (uint32_t)__half_as_ushort(__float2half_rn(v00))
                        | ((uint32_t)__half_as_ushort(__float2half_rn(v01)) << 16);
            uint32_t p1 = (uint32_t)__half_as_ushort(__float2half_rn(v10))
                        | ((uint32_t)__half_as_ushort(__float2half_rn(v11)) << 16);
            *reinterpret_cast<uint32_t*>(g_h1 + (size_t)ma * HID_ + n) = p0;
            *reinterpret_cast<uint32_t*>(g_h1 + (size_t)mb * HID_ + n) = p1;
        }
    }
}

// ========== GEMM2: split-K + fused last-CTA reduction ========================
// partial[z] = A[:, zseg] @ W2_f16[:, zseg]^T; last arriver per tile sums
// partials in fixed z order (+bias) -> out. Deterministic.
__global__ __launch_bounds__(128, 2)
void gemm2_hmma(const __grid_constant__ CUtensorMap a0,
                const __grid_constant__ CUtensorMap a1,
                const __grid_constant__ CUtensorMap b_m,
                const float* __restrict__ bias,
                float* __restrict__ outp)
{
    constexpr int NST = 2;
    constexpr uint32_t STG_A = 0;
    constexpr uint32_t STG_B = 16384;
    constexpr uint32_t STAGE_SZ = 32768;
    constexpr int T = KSEG / KC;    // 80

    extern __shared__ __align__(1024) char smem[];
    const uint32_t sbase = smem_u32(smem);
    __shared__ int s_old;

    const int tid  = threadIdx.x;
    const int lane = tid & 31;
    const int wid  = tid >> 5;
    const int wm   = (wid & 1) * 64;
    const int wn   = (wid >> 1) * 64;

    if (tid == 0) {
        #pragma unroll
        for (int s = 0; s < NST; s++) {
            MBARRIER_INIT(sbase + 8u * s, 1);
            MBARRIER_INIT(sbase + 64u + 8u * s, 4);
        }
        FENCE_PROXY_ASYNC();
    }
    __syncthreads();

    const int m0 = blockIdx.x * 128;
    const int n0 = blockIdx.y * 128;
    const int kb = blockIdx.z * KSEG;

    const uint32_t rowoff = (uint32_t)(lane & 15) * 128u;
    const uint32_t hi4 = (uint32_t)(lane >> 4);
    const uint32_t lo7 = (uint32_t)(lane & 7);
    uint32_t cb[4];
    #pragma unroll
    for (int ks = 0; ks < 4; ks++)
        cb[ks] = (((2u * ks + hi4) ^ lo7) << 4);

    float acc[4][8][4];
    #pragma unroll
    for (int mi = 0; mi < 4; mi++)
        #pragma unroll
        for (int ni = 0; ni < 8; ni++)
            #pragma unroll
            for (int q = 0; q < 4; q++) acc[mi][ni][q] = 0.f;

    if (tid == 0) {
        #pragma unroll
        for (int j = 0; j < NST; j++) {
            const uint32_t full = sbase + 8u * j;
            MBARRIER_EXPECT_TX(full, STAGE_SZ);
            const uint32_t sb = sbase + STAGE0_OFF + (uint32_t)j * STAGE_SZ;
            const int gk = kb + j * KC;
            if (gk < DIN_) tma2d(sb + STG_A, &a0, gk, m0, full);
            else           tma2d(sb + STG_A, &a1, gk - DIN_, m0, full);
            tma2d(sb + STG_B, &b_m, gk, n0, full);
        }
    }

    int s = 0, ph = 0;
    #pragma unroll 1
    for (int i = 0; i < T; i++) {
        MBARRIER_WAIT_PARITY(sbase + 8u * s, (uint32_t)ph);

        const uint32_t sb = sbase + STAGE0_OFF + (uint32_t)s * STAGE_SZ;
        const uint32_t aB = sb + STG_A + (uint32_t)wm * 128u + rowoff;
        const uint32_t bB = sb + STG_B + (uint32_t)wn * 128u + rowoff;

        STAGE_MMAS(aB, bB);

        if (lane == 0) MBARRIER_ARRIVE(sbase + 64u + 8u * s);

        const int j = i + NST;
        if (tid == 0 && j < T) {
            MBARRIER_WAIT_PARITY(sbase + 64u + 8u * s, (uint32_t)ph);
            const uint32_t full = sbase + 8u * s;
            MBARRIER_EXPECT_TX(full, STAGE_SZ);
            const int gk = kb + j * KC;
            if (gk < DIN_) tma2d(sb + STG_A, &a0, gk, m0, full);
            else           tma2d(sb + STG_A, &a1, gk - DIN_, m0, full);
            tma2d(sb + STG_B, &b_m, gk, n0, full);
        }
        if (++s == NST) { s = 0; ph ^= 1; }
    }

    // write fp32 partial (n padded to 1024; each slot written exactly once)
    float* part = g_p2 + (size_t)blockIdx.z * MB_ * 1024;
    const int mrow = m0 + wm + (lane >> 2);
    const int ncol = n0 + wn + 2 * (lane & 3);

    #pragma unroll
    for (int mi = 0; mi < 4; mi++) {
        #pragma unroll
        for (int ni = 0; ni < 8; ni++) {
            const int n = ncol + ni * 8;
            const int ma = mrow + mi * 16;
            const int mb = ma + 8;
            float2 o0 = { acc[mi][ni][0], acc[mi][ni][1] };
            float2 o1 = { acc[mi][ni][2], acc[mi][ni][3] };
            *reinterpret_cast<float2*>(part + (size_t)ma * 1024 + n) = o0;
            *reinterpret_cast<float2*>(part + (size_t)mb * 1024 + n) = o1;
        }
    }

    // ---- fused reduction: last CTA per (m-tile, n-tile) sums all partials ----
    __threadfence();
    __syncthreads();
    if (tid == 0)
        s_old = atomicAdd(&g_cnt[blockIdx.x * 8 + blockIdx.y], 1);
    __syncthreads();
    if (s_old == KSPLIT - 1) {
        __threadfence();   // acquire: other CTAs' partial writes now visible
        const int m = m0 + tid;                       // thread t -> row t
        const size_t rbase = (size_t)m * 1024 + n0;
        #pragma unroll 4
        for (int c = 0; c < 128; c += 2) {
            const int n = n0 + c;
            if (n >= ONN_) break;
            float2 sum = *reinterpret_cast<const float2*>(g_p2 + rbase + c);
            #pragma unroll
            for (int z = 1; z < KSPLIT; z++) {
                float2 v = *reinterpret_cast<const float2*>(
                    g_p2 + (size_t)z * MB_ * 1024 + rbase + c);
                sum.x += v.x; sum.y += v.y;
            }
            const float2 bv = __ldg(reinterpret_cast<const float2*>(bias + n));
            sum.x += bv.x; sum.y += bv.y;
            *reinterpret_cast<float2*>(outp + (size_t)m * ONN_ + n) = sum;
        }
    }
}

// ---------------- host side ---------------------
typedef CUresult (*PFN_tmap)(CUtensorMap*, CUtensorMapDataType, cuuint32_t, void*,
                             const cuuint64_t*, const cuuint64_t*, const cuuint32_t*,
                             const cuuint32_t*, CUtensorMapInterleave, CUtensorMapSwizzle,
                             CUtensorMapL2promotion, CUtensorMapFloatOOBfill);

static void mk2d(PFN_tmap f, CUtensorMap* m, void* p,
                 unsigned long long k, unsigned long long rows, unsigned box1)
{
    cuuint64_t dims[2] = { k, rows };
    cuuint64_t str[1]  = { k * 2 };
    cuuint32_t box[2]  = { 64u, box1 };
    cuuint32_t es[2]   = { 1u, 1u };
    f(m, CU_TENSOR_MAP_DATA_TYPE_FLOAT16, 2, p, dims, str, box, es,
      CU_TENSOR_MAP_INTERLEAVE_NONE, CU_TENSOR_MAP_SWIZZLE_128B,
      CU_TENSOR_MAP_L2_PROMOTION_L2_128B, CU_TENSOR_MAP_FLOAT_OOB_FILL_NONE);
}

extern "C" void kernel_launch(void* const* d_in, const int* in_sizes, int n_in,
                              void* d_out, int out_size)
{
    const float* x  = (const float*)d_in[0];
    const float* W1 = (const float*)d_in[1];
    const float* b1 = (const float*)d_in[2];
    const float* W2 = (const float*)d_in[3];
    const float* b2 = (const float*)d_in[4];
    float* out = (float*)d_out;

    void *xf, *w1f, *w2f, *h1, *cnt;
    cudaGetSymbolAddress(&xf,  g_xf);
    cudaGetSymbolAddress(&w1f, g_w1f);
    cudaGetSymbolAddress(&w2f, g_w2f);
    cudaGetSymbolAddress(&h1,  g_h1);
    cudaGetSymbolAddress(&cnt, g_cnt);

    // zero split-K counters (captured into the graph; replay-safe)
    cudaMemsetAsync(cnt, 0, 256 * sizeof(int));

    // merged fp32 -> fp16 conversion (one launch for x, W1, W2)
    {
        const size_t total = N4X + N4W1 + N4W2;
        conv_all<<<(unsigned)((total + 255) / 256), 256>>>(x, W1, W2);
    }

    PFN_tmap enc = nullptr;
    cudaDriverEntryPointQueryResult qr;
    cudaGetDriverEntryPoint("cuTensorMapEncodeTiled", (void**)&enc,
                            cudaEnableDefault, &qr);

    CUtensorMap m_x128, m_h1128, m_w1, m_w2;
    mk2d(enc, &m_x128,  xf, DIN_, MB_,  128);
    mk2d(enc, &m_h1128, h1, HID_, MB_,  128);
    mk2d(enc, &m_w1,    w1f, DIN_, HID_, 256);
    mk2d(enc, &m_w2,    w2f, K2_,  ONN_, 128);

    const int smem1 = STAGE0_OFF + 2 * 49152;   // 99328
    const int smem2 = STAGE0_OFF + 2 * 32768;   // 66560 -> 2 CTAs/SM
    cudaFuncSetAttribute(gemm1_hmma, cudaFuncAttributeMaxDynamicSharedMemorySize, smem1);
    cudaFuncSetAttribute(gemm2_hmma, cudaFuncAttributeMaxDynamicSharedMemorySize, smem2);

    // GEMM1: h1 = relu(x @ W1^T + b1)
    dim3 g1(MB_ / 128, HID_ / 256);   // (32, 64)
    gemm1_hmma<<<g1, 256, smem1>>>(m_x128, m_w1, b1);

    // GEMM2: split-K partials with fused last-CTA reduction
    dim3 g2(MB_ / 128, 8, KSPLIT);    // (32, 8, 4) = 1024 CTAs
    gemm2_hmma<<<g2, 128, smem2>>>(m_x128, m_h1128, m_w2, b2, out);
}

// round 13
// speedup vs baseline: 1.0311x; 1.0311x over previous
#include <cuda_runtime.h>
#include <cuda_fp16.h>
#include <cuda.h>
#include <cstdint>
#include <cstddef>

// ---------------- problem dims ----------------
#define MB_   4096
#define DIN_  4096
#define HID_  16384
#define ONN_  1000
#define K2_   (DIN_ + HID_)

#define KC 64                   // fp16 K per stage (128 B rows = SW128 atom)
#define STAGE0_OFF 1024
#define KSPLIT 4
#define KSEG   (K2_ / KSPLIT)   // 5120

// fp16 scratch (static device arrays — no allocation)
__device__ __align__(1024) __half g_xf [(size_t)MB_ * DIN_];
__device__ __align__(1024) __half g_w1f[(size_t)HID_ * DIN_];
__device__ __align__(1024) __half g_w2f[(size_t)ONN_ * K2_];
__device__ __align__(1024) __half g_h1 [(size_t)MB_ * HID_];
__device__ __align__(1024) float  g_p2 [(size_t)KSPLIT * MB_ * 1024];

// ---------------- PTX helpers ------------------
__device__ __forceinline__ uint32_t smem_u32(const void* p) {
    uint32_t a;
    asm("{ .reg .u64 t; cvta.to.shared.u64 t, %1; cvt.u32.u64 %0, t; }"
        : "=r"(a) : "l"(p));
    return a;
}

#define MBARRIER_INIT(addr, cnt) \
    asm volatile("mbarrier.init.shared.b64 [%0], %1;" :: "r"(addr), "r"(cnt) : "memory")

#define MBARRIER_EXPECT_TX(addr, bytes) \
    asm volatile("mbarrier.arrive.expect_tx.shared.b64 _, [%0], %1;" \
                 :: "r"(addr), "r"(bytes) : "memory")

#define MBARRIER_ARRIVE(addr) \
    asm volatile("mbarrier.arrive.shared.b64 _, [%0];" :: "r"(addr) : "memory")

#define MBARRIER_WAIT_PARITY(addr, parity) do {                                   \
    uint32_t _m = (addr); uint32_t _p = (parity); uint32_t _d;                    \
    asm volatile("{ .reg .pred p; mbarrier.try_wait.parity.acquire.cta.shared::cta.b64 p, [%1], %2; selp.b32 %0, 1, 0, p; }" \
        : "=r"(_d) : "r"(_m), "r"(_p) : "memory");                                \
    if (!_d) {                                                                    \
        asm volatile("{ .reg .pred P1; WL_%=: mbarrier.try_wait.parity.acquire.cta.shared::cta.b64 P1, [%0], %1, 0x989680; @P1 bra.uni WD_%=; bra.uni WL_%=; WD_%=: }" \
            :: "r"(_m), "r"(_p) : "memory");                                      \
    }                                                                             \
} while (0)

__device__ __forceinline__ void tma2d(uint32_t dst, const CUtensorMap* m,
                                      int cx, int cy, uint32_t mbar) {
    asm volatile(
        "cp.async.bulk.tensor.2d.shared::cta.global.tile.mbarrier::complete_tx::bytes "
        "[%0], [%1, {%2, %3}], [%4];"
        :: "r"(dst), "l"(m), "r"(cx), "r"(cy), "r"(mbar) : "memory");
}

#define FENCE_PROXY_ASYNC() asm volatile("fence.proxy.async.shared::cta;" ::: "memory")

__device__ __forceinline__ void ldsm4(uint32_t* r, uint32_t addr) {
    asm volatile("ldmatrix.sync.aligned.m8n8.x4.shared.b16 {%0,%1,%2,%3}, [%4];"
                 : "=r"(r[0]), "=r"(r[1]), "=r"(r[2]), "=r"(r[3]) : "r"(addr));
}

__device__ __forceinline__ void mma16816(float* c, const uint32_t* a, uint32_t b0, uint32_t b1) {
    asm volatile(
        "mma.sync.aligned.m16n8k16.row.col.f32.f16.f16.f32 "
        "{%0,%1,%2,%3}, {%4,%5,%6,%7}, {%8,%9}, {%0,%1,%2,%3};"
        : "+f"(c[0]), "+f"(c[1]), "+f"(c[2]), "+f"(c[3])
        : "r"(a[0]), "r"(a[1]), "r"(a[2]), "r"(a[3]), "r"(b0), "r"(b1));
}

// ---------------- merged conversion (x, W1, W2 in one launch, 8 floats/thr) --
#define N8X  ((size_t)MB_  * DIN_ / 8)
#define N8W1 ((size_t)HID_ * DIN_ / 8)
#define N8W2 ((size_t)ONN_ * K2_  / 8)

__device__ __forceinline__ uint2 pack_f16x4(float4 v) {
    uint2 p;
    p.x = (uint32_t)__half_as_ushort(__float2half_rn(v.x))
        | ((uint32_t)__half_as_ushort(__float2half_rn(v.y)) << 16);
    p.y = (uint32_t)__half_as_ushort(__float2half_rn(v.z))
        | ((uint32_t)__half_as_ushort(__float2half_rn(v.w)) << 16);
    return p;
}

__global__ __launch_bounds__(256)
void conv_all(const float* __restrict__ x,
              const float* __restrict__ w1,
              const float* __restrict__ w2)
{
    size_t i = (size_t)blockIdx.x * blockDim.x + threadIdx.x;
    const float* src;
    __half* dst;
    if (i < N8X)                    { src = x;  dst = g_xf;  }
    else if (i < N8X + N8W1)        { src = w1; dst = g_w1f; i -= N8X; }
    else if (i < N8X + N8W1 + N8W2) { src = w2; dst = g_w2f; i -= N8X + N8W1; }
    else return;

    // two independent float4 loads in flight (MLP=2)
    float4 v0 = reinterpret_cast<const float4*>(src)[2 * i];
    float4 v1 = reinterpret_cast<const float4*>(src)[2 * i + 1];
    uint4 o;
    uint2 p0 = pack_f16x4(v0);
    uint2 p1 = pack_f16x4(v1);
    o.x = p0.x; o.y = p0.y; o.z = p1.x; o.w = p1.y;
    reinterpret_cast<uint4*>(dst)[i] = o;
}

// mainloop body with register fragment double-buffering (4 k16 slices/stage)
#define STAGE_MMAS(aB, bB)                                                        \
    do {                                                                          \
        uint32_t aa[2][4][4], bb[2][4][4];                                        \
        _Pragma("unroll")                                                         \
        for (int mi = 0; mi < 4; mi++)                                            \
            ldsm4(aa[0][mi], (aB) + (uint32_t)mi * 2048u + cb[0]);                \
        _Pragma("unroll")                                                         \
        for (int nj = 0; nj < 4; nj++)                                            \
            ldsm4(bb[0][nj], (bB) + (uint32_t)nj * 2048u + cb[0]);                \
        _Pragma("unroll")                                                         \
        for (int ks = 0; ks < 4; ks++) {                                          \
            const int cur = ks & 1, nxt = cur ^ 1;                                \
            if (ks < 3) {                                                         \
                _Pragma("unroll")                                                 \
                for (int mi = 0; mi < 4; mi++)                                    \
                    ldsm4(aa[nxt][mi], (aB) + (uint32_t)mi * 2048u + cb[ks + 1]); \
                _Pragma("unroll")                                                 \
                for (int nj = 0; nj < 4; nj++)                                    \
                    ldsm4(bb[nxt][nj], (bB) + (uint32_t)nj * 2048u + cb[ks + 1]); \
            }                                                                     \
            _Pragma("unroll")                                                     \
            for (int mi = 0; mi < 4; mi++)                                        \
                _Pragma("unroll")                                                 \
                for (int ni = 0; ni < 8; ni++) {                                  \
                    const uint32_t b0 = bb[cur][ni >> 1][ni & 1];                 \
                    const uint32_t b1 = bb[cur][ni >> 1][(ni & 1) + 2];           \
                    mma16816(acc[mi][ni], aa[cur][mi], b0, b1);                   \
                }                                                                 \
        }                                                                         \
    } while (0)

// ======================= GEMM1: BM=128 x BN=256, warp tile 64x64 =============
// h1 = relu(x_f16 @ W1_f16^T + b1) -> fp16, single pass   [unchanged winner]
__global__ __launch_bounds__(256, 1)
void gemm1_hmma(const __grid_constant__ CUtensorMap a_m,
                const __grid_constant__ CUtensorMap b_m,
                const float* __restrict__ bias)
{
    constexpr int NST = 2;
    constexpr uint32_t STG_A = 0;
    constexpr uint32_t STG_B = 16384;
    constexpr uint32_t STAGE_SZ = 49152;

    extern __shared__ __align__(1024) char smem[];
    const uint32_t sbase = smem_u32(smem);

    const int tid  = threadIdx.x;
    const int lane = tid & 31;
    const int wid  = tid >> 5;
    const int wm   = (wid & 1) * 64;
    const int wn   = (wid >> 1) * 64;

    if (tid == 0) {
        #pragma unroll
        for (int s = 0; s < NST; s++) {
            MBARRIER_INIT(sbase + 8u * s, 1);
            MBARRIER_INIT(sbase + 64u + 8u * s, 8);
        }
        FENCE_PROXY_ASYNC();
    }
    __syncthreads();

    const int m0 = blockIdx.x * 128;
    const int n0 = blockIdx.y * 256;
    const int T  = DIN_ / KC;

    const uint32_t rowoff = (uint32_t)(lane & 15) * 128u;
    const uint32_t hi4 = (uint32_t)(lane >> 4);
    const uint32_t lo7 = (uint32_t)(lane & 7);
    uint32_t cb[4];
    #pragma unroll
    for (int ks = 0; ks < 4; ks++)
        cb[ks] = (((2u * ks + hi4) ^ lo7) << 4);

    float acc[4][8][4];
    #pragma unroll
    for (int mi = 0; mi < 4; mi++)
        #pragma unroll
        for (int ni = 0; ni < 8; ni++)
            #pragma unroll
            for (int q = 0; q < 4; q++) acc[mi][ni][q] = 0.f;

    if (tid == 0) {
        #pragma unroll
        for (int j = 0; j < NST; j++) {
            const uint32_t full = sbase + 8u * j;
            MBARRIER_EXPECT_TX(full, STAGE_SZ);
            const uint32_t sb = sbase + STAGE0_OFF + (uint32_t)j * STAGE_SZ;
            tma2d(sb + STG_A, &a_m, j * KC, m0, full);
            tma2d(sb + STG_B, &b_m, j * KC, n0, full);
        }
    }

    int s = 0, ph = 0;
    #pragma unroll 1
    for (int i = 0; i < T; i++) {
        MBARRIER_WAIT_PARITY(sbase + 8u * s, (uint32_t)ph);

        const uint32_t sb = sbase + STAGE0_OFF + (uint32_t)s * STAGE_SZ;
        const uint32_t aB = sb + STG_A + (uint32_t)wm * 128u + rowoff;
        const uint32_t bB = sb + STG_B + (uint32_t)wn * 128u + rowoff;

        STAGE_MMAS(aB, bB);

        if (lane == 0) MBARRIER_ARRIVE(sbase + 64u + 8u * s);

        const int j = i + NST;
        if (tid == 0 && j < T) {
            MBARRIER_WAIT_PARITY(sbase + 64u + 8u * s, (uint32_t)ph);
            const uint32_t full = sbase + 8u * s;
            MBARRIER_EXPECT_TX(full, STAGE_SZ);
            tma2d(sb + STG_A, &a_m, j * KC, m0, full);
            tma2d(sb + STG_B, &b_m, j * KC, n0, full);
        }
        if (++s == NST) { s = 0; ph ^= 1; }
    }

    const int mrow = m0 + wm + (lane >> 2);
    const int ncol = n0 + wn + 2 * (lane & 3);

    #pragma unroll
    for (int mi = 0; mi < 4; mi++) {
        #pragma unroll
        for (int ni = 0; ni < 8; ni++) {
            const int n = ncol + ni * 8;
            const int ma = mrow + mi * 16;
            const int mb = ma + 8;
            const float2 bv = __ldg(reinterpret_cast<const float2*>(bias + n));
            float v00 = acc[mi][ni][0] + bv.x;
            float v01 = acc[mi][ni][1] + bv.y;
            float v10 = acc[mi][ni][2] + bv.x;
            float v11 = acc[mi][ni][3] + bv.y;
            v00 = v00 > 0.f ? v00 : 0.f;
            v01 = v01 > 0.f ? v01 : 0.f;
            v10 = v10 > 0.f ? v10 : 0.f;
            v11 = v11 > 0.f ? v11 : 0.f;
            uint32_t p0 = (uint32_t)__half_as_ushort(__float2half_rn(v00))
                        | ((uint32_t)__half_as_ushort(__float2half_rn(v01)) << 16);
            uint32_t p1 = (uint32_t)__half_as_ushort(__float2half_rn(v10))
                        | ((uint32_t)__half_as_ushort(__float2half_rn(v11)) << 16);
            *reinterpret_cast<uint32_t*>(g_h1 + (size_t)ma * HID_ + n) = p0;
            *reinterpret_cast<uint32_t*>(g_h1 + (size_t)mb * HID_ + n) = p1;
        }
    }
}

// ========== GEMM2: split-K, TBM=128 x BN=128, 4 warps, warp tile 64x64 =======
// partial[z] = A[:, zseg] @ W2_f16[:, zseg]^T, single pass   [R10 winner]
__global__ __launch_bounds__(128, 2)
void gemm2_hmma(const __grid_constant__ CUtensorMap a0,
                const __grid_constant__ CUtensorMap a1,
                const __grid_constant__ CUtensorMap b_m)
{
    constexpr int NST = 2;
    constexpr uint32_t STG_A = 0;
    constexpr uint32_t STG_B = 16384;
    constexpr uint32_t STAGE_SZ = 32768;
    constexpr int T = KSEG / KC;    // 80

    extern __shared__ __align__(1024) char smem[];
    const uint32_t sbase = smem_u32(smem);

    const int tid  = threadIdx.x;
    const int lane = tid & 31;
    const int wid  = tid >> 5;
    const int wm   = (wid & 1) * 64;
    const int wn   = (wid >> 1) * 64;

    if (tid == 0) {
        #pragma unroll
        for (int s = 0; s < NST; s++) {
            MBARRIER_INIT(sbase + 8u * s, 1);
            MBARRIER_INIT(sbase + 64u + 8u * s, 4);
        }
        FENCE_PROXY_ASYNC();
    }
    __syncthreads();

    const int m0 = blockIdx.x * 128;
    const int n0 = blockIdx.y * 128;
    const int kb = blockIdx.z * KSEG;

    const uint32_t rowoff = (uint32_t)(lane & 15) * 128u;
    const uint32_t hi4 = (uint32_t)(lane >> 4);
    const uint32_t lo7 = (uint32_t)(lane & 7);
    uint32_t cb[4];
    #pragma unroll
    for (int ks = 0; ks < 4; ks++)
        cb[ks] = (((2u * ks + hi4) ^ lo7) << 4);

    float acc[4][8][4];
    #pragma unroll
    for (int mi = 0; mi < 4; mi++)
        #pragma unroll
        for (int ni = 0; ni < 8; ni++)
            #pragma unroll
            for (int q = 0; q < 4; q++) acc[mi][ni][q] = 0.f;

    if (tid == 0) {
        #pragma unroll
        for (int j = 0; j < NST; j++) {
            const uint32_t full = sbase + 8u * j;
            MBARRIER_EXPECT_TX(full, STAGE_SZ);
            const uint32_t sb = sbase + STAGE0_OFF + (uint32_t)j * STAGE_SZ;
            const int gk = kb + j * KC;
            if (gk < DIN_) tma2d(sb + STG_A, &a0, gk, m0, full);
            else           tma2d(sb + STG_A, &a1, gk - DIN_, m0, full);
            tma2d(sb + STG_B, &b_m, gk, n0, full);
        }
    }

    int s = 0, ph = 0;
    #pragma unroll 1
    for (int i = 0; i < T; i++) {
        MBARRIER_WAIT_PARITY(sbase + 8u * s, (uint32_t)ph);

        const uint32_t sb = sbase + STAGE0_OFF + (uint32_t)s * STAGE_SZ;
        const uint32_t aB = sb + STG_A + (uint32_t)wm * 128u + rowoff;
        const uint32_t bB = sb + STG_B + (uint32_t)wn * 128u + rowoff;

        STAGE_MMAS(aB, bB);

        if (lane == 0) MBARRIER_ARRIVE(sbase + 64u + 8u * s);

        const int j = i + NST;
        if (tid == 0 && j < T) {
            MBARRIER_WAIT_PARITY(sbase + 64u + 8u * s, (uint32_t)ph);
            const uint32_t full = sbase + 8u * s;
            MBARRIER_EXPECT_TX(full, STAGE_SZ);
            const int gk = kb + j * KC;
            if (gk < DIN_) tma2d(sb + STG_A, &a0, gk, m0, full);
            else           tma2d(sb + STG_A, &a1, gk - DIN_, m0, full);
            tma2d(sb + STG_B, &b_m, gk, n0, full);
        }
        if (++s == NST) { s = 0; ph ^= 1; }
    }

    // write fp32 partial (n padded to 1024; each slot written exactly once)
    float* part = g_p2 + (size_t)blockIdx.z * MB_ * 1024;
    const int mrow = m0 + wm + (lane >> 2);
    const int ncol = n0 + wn + 2 * (lane & 3);

    #pragma unroll
    for (int mi = 0; mi < 4; mi++) {
        #pragma unroll
        for (int ni = 0; ni < 8; ni++) {
            const int n = ncol + ni * 8;
            const int ma = mrow + mi * 16;
            const int mb = ma + 8;
            float2 o0 = { acc[mi][ni][0], acc[mi][ni][1] };
            float2 o1 = { acc[mi][ni][2], acc[mi][ni][3] };
            *reinterpret_cast<float2*>(part + (size_t)ma * 1024 + n) = o0;
            *reinterpret_cast<float2*>(part + (size_t)mb * 1024 + n) = o1;
        }
    }
}

// reduce partials + bias -> out (float4 wide)
__global__ __launch_bounds__(256)
void reduce_k(const float* __restrict__ bias, float* __restrict__ outp)
{
    const size_t i = (size_t)blockIdx.x * blockDim.x + threadIdx.x;   // 4096*250
    if (i >= (size_t)MB_ * (ONN_ / 4)) return;
    const int m = (int)(i / (ONN_ / 4));
    const int n = 4 * (int)(i % (ONN_ / 4));
    const size_t off = (size_t)m * 1024 + n;
    float4 s = *reinterpret_cast<const float4*>(g_p2 + off);
    #pragma unroll
    for (int z = 1; z < KSPLIT; z++) {
        float4 v = *reinterpret_cast<const float4*>(g_p2 + (size_t)z * MB_ * 1024 + off);
        s.x += v.x; s.y += v.y; s.z += v.z; s.w += v.w;
    }
    const float4 bv = __ldg(reinterpret_cast<const float4*>(bias + n));
    s.x += bv.x; s.y += bv.y; s.z += bv.z; s.w += bv.w;
    *reinterpret_cast<float4*>(outp + (size_t)m * ONN_ + n) = s;
}

// ---------------- host side ---------------------
typedef CUresult (*PFN_tmap)(CUtensorMap*, CUtensorMapDataType, cuuint32_t, void*,
                             const cuuint64_t*, const cuuint64_t*, const cuuint32_t*,
                             const cuuint32_t*, CUtensorMapInterleave, CUtensorMapSwizzle,
                             CUtensorMapL2promotion, CUtensorMapFloatOOBfill);

static void mk2d(PFN_tmap f, CUtensorMap* m, void* p,
                 unsigned long long k, unsigned long long rows, unsigned box1)
{
    cuuint64_t dims[2] = { k, rows };
    cuuint64_t str[1]  = { k * 2 };
    cuuint32_t box[2]  = { 64u, box1 };
    cuuint32_t es[2]   = { 1u, 1u };
    f(m, CU_TENSOR_MAP_DATA_TYPE_FLOAT16, 2, p, dims, str, box, es,
      CU_TENSOR_MAP_INTERLEAVE_NONE, CU_TENSOR_MAP_SWIZZLE_128B,
      CU_TENSOR_MAP_L2_PROMOTION_L2_128B, CU_TENSOR_MAP_FLOAT_OOB_FILL_NONE);
}

extern "C" void kernel_launch(void* const* d_in, const int* in_sizes, int n_in,
                              void* d_out, int out_size)
{
    const float* x  = (const float*)d_in[0];
    const float* W1 = (const float*)d_in[1];
    const float* b1 = (const float*)d_in[2];
    const float* W2 = (const float*)d_in[3];
    const float* b2 = (const float*)d_in[4];
    float* out = (float*)d_out;

    void *xf, *w1f, *w2f, *h1;
    cudaGetSymbolAddress(&xf,  g_xf);
    cudaGetSymbolAddress(&w1f, g_w1f);
    cudaGetSymbolAddress(&w2f, g_w2f);
    cudaGetSymbolAddress(&h1,  g_h1);

    // merged fp32 -> fp16 conversion (one launch; 8 floats per thread)
    {
        const size_t total = N8X + N8W1 + N8W2;
        conv_all<<<(unsigned)((total + 255) / 256), 256>>>(x, W1, W2);
    }

    PFN_tmap enc = nullptr;
    cudaDriverEntryPointQueryResult qr;
    cudaGetDriverEntryPoint("cuTensorMapEncodeTiled", (void**)&enc,
                            cudaEnableDefault, &qr);

    CUtensorMap m_x128, m_h1128, m_w1, m_w2;
    mk2d(enc, &m_x128,  xf, DIN_, MB_,  128);
    mk2d(enc, &m_h1128, h1, HID_, MB_,  128);
    mk2d(enc, &m_w1,    w1f, DIN_, HID_, 256);
    mk2d(enc, &m_w2,    w2f, K2_,  ONN_, 128);

    const int smem1 = STAGE0_OFF + 2 * 49152;   // 99328
    const int smem2 = STAGE0_OFF + 2 * 32768;   // 66560 -> 2 CTAs/SM
    cudaFuncSetAttribute(gemm1_hmma, cudaFuncAttributeMaxDynamicSharedMemorySize, smem1);
    cudaFuncSetAttribute(gemm2_hmma, cudaFuncAttributeMaxDynamicSharedMemorySize, smem2);

    // GEMM1: h1 = relu(x @ W1^T + b1)
    dim3 g1(MB_ / 128, HID_ / 256);   // (32, 64)
    gemm1_hmma<<<g1, 256, smem1>>>(m_x128, m_w1, b1);

    // GEMM2: split-K partials, then reduce
    dim3 g2(MB_ / 128, 8, KSPLIT);    // (32, 8, 4) = 1024 CTAs
    gemm2_hmma<<<g2, 128, smem2>>>(m_x128, m_h1128, m_w2);

    const size_t nred = (size_t)MB_ * (ONN_ / 4);
    reduce_k<<<(unsigned)((nred + 255) / 256), 256>>>(b2, out);
}

// round 14
// speedup vs baseline: 1.0685x; 1.0363x over previous
#include <cuda_runtime.h>
#include <cuda_fp16.h>
#include <cuda.h>
#include <cstdint>
#include <cstddef>

// ---------------- problem dims ----------------
#define MB_   4096
#define DIN_  4096
#define HID_  16384
#define ONN_  1000
#define K2_   (DIN_ + HID_)

#define KC 64                   // fp16 K per stage (128 B rows = SW128 atom)
#define STAGE0_OFF 1024
#define KSPLIT 4
#define KSEG   (K2_ / KSPLIT)   // 5120

// fp16 scratch (static device arrays — no allocation)
__device__ __align__(1024) __half g_xf [(size_t)MB_ * DIN_];
__device__ __align__(1024) __half g_w1f[(size_t)HID_ * DIN_];
__device__ __align__(1024) __half g_w2f[(size_t)ONN_ * K2_];
__device__ __align__(1024) __half g_h1 [(size_t)MB_ * HID_];
__device__ __align__(1024) float  g_p2 [(size_t)KSPLIT * MB_ * 1024];

// ---------------- PTX helpers ------------------
__device__ __forceinline__ uint32_t smem_u32(const void* p) {
    uint32_t a;
    asm("{ .reg .u64 t; cvta.to.shared.u64 t, %1; cvt.u32.u64 %0, t; }"
        : "=r"(a) : "l"(p));
    return a;
}

#define MBARRIER_INIT(addr, cnt) \
    asm volatile("mbarrier.init.shared.b64 [%0], %1;" :: "r"(addr), "r"(cnt) : "memory")

#define MBARRIER_EXPECT_TX(addr, bytes) \
    asm volatile("mbarrier.arrive.expect_tx.shared.b64 _, [%0], %1;" \
                 :: "r"(addr), "r"(bytes) : "memory")

#define MBARRIER_ARRIVE(addr) \
    asm volatile("mbarrier.arrive.shared.b64 _, [%0];" :: "r"(addr) : "memory")

#define MBARRIER_WAIT_PARITY(addr, parity) do {                                   \
    uint32_t _m = (addr); uint32_t _p = (parity); uint32_t _d;                    \
    asm volatile("{ .reg .pred p; mbarrier.try_wait.parity.acquire.cta.shared::cta.b64 p, [%1], %2; selp.b32 %0, 1, 0, p; }" \
        : "=r"(_d) : "r"(_m), "r"(_p) : "memory");                                \
    if (!_d) {                                                                    \
        asm volatile("{ .reg .pred P1; WL_%=: mbarrier.try_wait.parity.acquire.cta.shared::cta.b64 P1, [%0], %1, 0x989680; @P1 bra.uni WD_%=; bra.uni WL_%=; WD_%=: }" \
            :: "r"(_m), "r"(_p) : "memory");                                      \
    }                                                                             \
} while (0)

__device__ __forceinline__ void tma2d(uint32_t dst, const CUtensorMap* m,
                                      int cx, int cy, uint32_t mbar) {
    asm volatile(
        "cp.async.bulk.tensor.2d.shared::cta.global.tile.mbarrier::complete_tx::bytes "
        "[%0], [%1, {%2, %3}], [%4];"
        :: "r"(dst), "l"(m), "r"(cx), "r"(cy), "r"(mbar) : "memory");
}

#define FENCE_PROXY_ASYNC() asm volatile("fence.proxy.async.shared::cta;" ::: "memory")

__device__ __forceinline__ void ldsm4(uint32_t* r, uint32_t addr) {
    asm volatile("ldmatrix.sync.aligned.m8n8.x4.shared.b16 {%0,%1,%2,%3}, [%4];"
                 : "=r"(r[0]), "=r"(r[1]), "=r"(r[2]), "=r"(r[3]) : "r"(addr));
}

__device__ __forceinline__ void mma16816(float* c, const uint32_t* a, uint32_t b0, uint32_t b1) {
    asm volatile(
        "mma.sync.aligned.m16n8k16.row.col.f32.f16.f16.f32 "
        "{%0,%1,%2,%3}, {%4,%5,%6,%7}, {%8,%9}, {%0,%1,%2,%3};"
        : "+f"(c[0]), "+f"(c[1]), "+f"(c[2]), "+f"(c[3])
        : "r"(a[0]), "r"(a[1]), "r"(a[2]), "r"(a[3]), "r"(b0), "r"(b1));
}

// ---------------- merged conversion (x, W1, W2 in one launch, 8 floats/thr) --
#define N8X  ((size_t)MB_  * DIN_ / 8)
#define N8W1 ((size_t)HID_ * DIN_ / 8)
#define N8W2 ((size_t)ONN_ * K2_  / 8)

__device__ __forceinline__ uint2 pack_f16x4(float4 v) {
    uint2 p;
    p.x = (uint32_t)__half_as_ushort(__float2half_rn(v.x))
        | ((uint32_t)__half_as_ushort(__float2half_rn(v.y)) << 16);
    p.y = (uint32_t)__half_as_ushort(__float2half_rn(v.z))
        | ((uint32_t)__half_as_ushort(__float2half_rn(v.w)) << 16);
    return p;
}

__global__ __launch_bounds__(256)
void conv_all(const float* __restrict__ x,
              const float* __restrict__ w1,
              const float* __restrict__ w2)
{
    size_t i = (size_t)blockIdx.x * blockDim.x + threadIdx.x;
    const float* src;
    __half* dst;
    if (i < N8X)                    { src = x;  dst = g_xf;  }
    else if (i < N8X + N8W1)        { src = w1; dst = g_w1f; i -= N8X; }
    else if (i < N8X + N8W1 + N8W2) { src = w2; dst = g_w2f; i -= N8X + N8W1; }
    else return;

    float4 v0 = reinterpret_cast<const float4*>(src)[2 * i];
    float4 v1 = reinterpret_cast<const float4*>(src)[2 * i + 1];
    uint4 o;
    uint2 p0 = pack_f16x4(v0);
    uint2 p1 = pack_f16x4(v1);
    o.x = p0.x; o.y = p0.y; o.z = p1.x; o.w = p1.y;
    reinterpret_cast<uint4*>(dst)[i] = o;
}

// ======================= GEMM1: BM=128 x BN=64, 4 warps, 3 CTAs/SM ===========
// warp tile 64x32; 12 warps/SM (3 per SMSP) to cover HMMA issue gaps.
// h1 = relu(x_f16 @ W1_f16^T + b1) -> fp16
__global__ __launch_bounds__(128, 3)
void gemm1_hmma(const __grid_constant__ CUtensorMap a_m,
                const __grid_constant__ CUtensorMap b_m,
                const float* __restrict__ bias)
{
    constexpr int NST = 2;
    constexpr uint32_t STG_A = 0;
    constexpr uint32_t STG_B = 16384;        // A is 128*128 = 16KB
    constexpr uint32_t STAGE_SZ = 24576;     // 16K A + 8K B

    extern __shared__ __align__(1024) char smem[];
    const uint32_t sbase = smem_u32(smem);

    const int tid  = threadIdx.x;
    const int lane = tid & 31;
    const int wid  = tid >> 5;
    const int wm   = (wid & 1) * 64;
    const int wn   = (wid >> 1) * 32;

    if (tid == 0) {
        #pragma unroll
        for (int s = 0; s < NST; s++) {
            MBARRIER_INIT(sbase + 8u * s, 1);
            MBARRIER_INIT(sbase + 64u + 8u * s, 4);
        }
        FENCE_PROXY_ASYNC();
    }
    __syncthreads();

    const int m0 = blockIdx.x * 128;
    const int n0 = blockIdx.y * 64;
    const int T  = DIN_ / KC;    // 64

    const uint32_t rowoff = (uint32_t)(lane & 15) * 128u;
    const uint32_t hi4 = (uint32_t)(lane >> 4);
    const uint32_t lo7 = (uint32_t)(lane & 7);
    uint32_t cb[4];
    #pragma unroll
    for (int ks = 0; ks < 4; ks++)
        cb[ks] = (((2u * ks + hi4) ^ lo7) << 4);

    float acc[4][4][4];
    #pragma unroll
    for (int mi = 0; mi < 4; mi++)
        #pragma unroll
        for (int ni = 0; ni < 4; ni++)
            #pragma unroll
            for (int q = 0; q < 4; q++) acc[mi][ni][q] = 0.f;

    if (tid == 0) {
        #pragma unroll
        for (int j = 0; j < NST; j++) {
            const uint32_t full = sbase + 8u * j;
            MBARRIER_EXPECT_TX(full, STAGE_SZ);
            const uint32_t sb = sbase + STAGE0_OFF + (uint32_t)j * STAGE_SZ;
            tma2d(sb + STG_A, &a_m, j * KC, m0, full);
            tma2d(sb + STG_B, &b_m, j * KC, n0, full);
        }
    }

    int s = 0, ph = 0;
    #pragma unroll 1
    for (int i = 0; i < T; i++) {
        MBARRIER_WAIT_PARITY(sbase + 8u * s, (uint32_t)ph);

        const uint32_t sb = sbase + STAGE0_OFF + (uint32_t)s * STAGE_SZ;
        const uint32_t aB = sb + STG_A + (uint32_t)wm * 128u + rowoff;
        const uint32_t bB = sb + STG_B + (uint32_t)wn * 128u + rowoff;

        #pragma unroll
        for (int ks = 0; ks < 4; ks++) {
            uint32_t aa[4][4], bb[2][4];
            #pragma unroll
            for (int mi = 0; mi < 4; mi++)
                ldsm4(aa[mi], aB + (uint32_t)mi * 2048u + cb[ks]);
            #pragma unroll
            for (int nj = 0; nj < 2; nj++)
                ldsm4(bb[nj], bB + (uint32_t)nj * 2048u + cb[ks]);

            #pragma unroll
            for (int mi = 0; mi < 4; mi++)
                #pragma unroll
                for (int ni = 0; ni < 4; ni++) {
                    const uint32_t b0 = bb[ni >> 1][ni & 1];
                    const uint32_t b1 = bb[ni >> 1][(ni & 1) + 2];
                    mma16816(acc[mi][ni], aa[mi], b0, b1);
                }
        }

        if (lane == 0) MBARRIER_ARRIVE(sbase + 64u + 8u * s);

        const int j = i + NST;
        if (tid == 0 && j < T) {
            MBARRIER_WAIT_PARITY(sbase + 64u + 8u * s, (uint32_t)ph);
            const uint32_t full = sbase + 8u * s;
            MBARRIER_EXPECT_TX(full, STAGE_SZ);
            tma2d(sb + STG_A, &a_m, j * KC, m0, full);
            tma2d(sb + STG_B, &b_m, j * KC, n0, full);
        }
        if (++s == NST) { s = 0; ph ^= 1; }
    }

    // epilogue: bias + relu -> fp16
    const int mrow = m0 + wm + (lane >> 2);
    const int ncol = n0 + wn + 2 * (lane & 3);

    #pragma unroll
    for (int mi = 0; mi < 4; mi++) {
        #pragma unroll
        for (int ni = 0; ni < 4; ni++) {
            const int n = ncol + ni * 8;
            const int ma = mrow + mi * 16;
            const int mb = ma + 8;
            const float2 bv = __ldg(reinterpret_cast<const float2*>(bias + n));
            float v00 = acc[mi][ni][0] + bv.x;
            float v01 = acc[mi][ni][1] + bv.y;
            float v10 = acc[mi][ni][2] + bv.x;
            float v11 = acc[mi][ni][3] + bv.y;
            v00 = v00 > 0.f ? v00 : 0.f;
            v01 = v01 > 0.f ? v01 : 0.f;
            v10 = v10 > 0.f ? v10 : 0.f;
            v11 = v11 > 0.f ? v11 : 0.f;
            uint32_t p0 = (uint32_t)__half_as_ushort(__float2half_rn(v00))
                        | ((uint32_t)__half_as_ushort(__float2half_rn(v01)) << 16);
            uint32_t p1 = (uint32_t)__half_as_ushort(__float2half_rn(v10))
                        | ((uint32_t)__half_as_ushort(__float2half_rn(v11)) << 16);
            *reinterpret_cast<uint32_t*>(g_h1 + (size_t)ma * HID_ + n) = p0;
            *reinterpret_cast<uint32_t*>(g_h1 + (size_t)mb * HID_ + n) = p1;
        }
    }
}

// ========== GEMM2: split-K, TBM=128 x BN=128, 4 warps, warp tile 64x64 =======
// partial[z] = A[:, zseg] @ W2_f16[:, zseg]^T, single pass   [R10/R13 winner]
__global__ __launch_bounds__(128, 2)
void gemm2_hmma(const __grid_constant__ CUtensorMap a0,
                const __grid_constant__ CUtensorMap a1,
                const __grid_constant__ CUtensorMap b_m)
{
    constexpr int NST = 2;
    constexpr uint32_t STG_A = 0;
    constexpr uint32_t STG_B = 16384;
    constexpr uint32_t STAGE_SZ = 32768;
    constexpr int T = KSEG / KC;    // 80

    extern __shared__ __align__(1024) char smem[];
    const uint32_t sbase = smem_u32(smem);

    const int tid  = threadIdx.x;
    const int lane = tid & 31;
    const int wid  = tid >> 5;
    const int wm   = (wid & 1) * 64;
    const int wn   = (wid >> 1) * 64;

    if (tid == 0) {
        #pragma unroll
        for (int s = 0; s < NST; s++) {
            MBARRIER_INIT(sbase + 8u * s, 1);
            MBARRIER_INIT(sbase + 64u + 8u * s, 4);
        }
        FENCE_PROXY_ASYNC();
    }
    __syncthreads();

    const int m0 = blockIdx.x * 128;
    const int n0 = blockIdx.y * 128;
    const int kb = blockIdx.z * KSEG;

    const uint32_t rowoff = (uint32_t)(lane & 15) * 128u;
    const uint32_t hi4 = (uint32_t)(lane >> 4);
    const uint32_t lo7 = (uint32_t)(lane & 7);
    uint32_t cb[4];
    #pragma unroll
    for (int ks = 0; ks < 4; ks++)
        cb[ks] = (((2u * ks + hi4) ^ lo7) << 4);

    float acc[4][8][4];
    #pragma unroll
    for (int mi = 0; mi < 4; mi++)
        #pragma unroll
        for (int ni = 0; ni < 8; ni++)
            #pragma unroll
            for (int q = 0; q < 4; q++) acc[mi][ni][q] = 0.f;

    if (tid == 0) {
        #pragma unroll
        for (int j = 0; j < NST; j++) {
            const uint32_t full = sbase + 8u * j;
            MBARRIER_EXPECT_TX(full, STAGE_SZ);
            const uint32_t sb = sbase + STAGE0_OFF + (uint32_t)j * STAGE_SZ;
            const int gk = kb + j * KC;
            if (gk < DIN_) tma2d(sb + STG_A, &a0, gk, m0, full);
            else           tma2d(sb + STG_A, &a1, gk - DIN_, m0, full);
            tma2d(sb + STG_B, &b_m, gk, n0, full);
        }
    }

    int s = 0, ph = 0;
    #pragma unroll 1
    for (int i = 0; i < T; i++) {
        MBARRIER_WAIT_PARITY(sbase + 8u * s, (uint32_t)ph);

        const uint32_t sb = sbase + STAGE0_OFF + (uint32_t)s * STAGE_SZ;
        const uint32_t aB = sb + STG_A + (uint32_t)wm * 128u + rowoff;
        const uint32_t bB = sb + STG_B + (uint32_t)wn * 128u + rowoff;

        #pragma unroll
        for (int ks = 0; ks < 4; ks++) {
            uint32_t aa[4][4], bb[4][4];
            #pragma unroll
            for (int mi = 0; mi < 4; mi++)
                ldsm4(aa[mi], aB + (uint32_t)mi * 2048u + cb[ks]);
            #pragma unroll
            for (int nj = 0; nj < 4; nj++)
                ldsm4(bb[nj], bB + (uint32_t)nj * 2048u + cb[ks]);

            #pragma unroll
            for (int mi = 0; mi < 4; mi++)
                #pragma unroll
                for (int ni = 0; ni < 8; ni++) {
                    const uint32_t b0 = bb[ni >> 1][ni & 1];
                    const uint32_t b1 = bb[ni >> 1][(ni & 1) + 2];
                    mma16816(acc[mi][ni], aa[mi], b0, b1);
                }
        }

        if (lane == 0) MBARRIER_ARRIVE(sbase + 64u + 8u * s);

        const int j = i + NST;
        if (tid == 0 && j < T) {
            MBARRIER_WAIT_PARITY(sbase + 64u + 8u * s, (uint32_t)ph);
            const uint32_t full = sbase + 8u * s;
            MBARRIER_EXPECT_TX(full, STAGE_SZ);
            const int gk = kb + j * KC;
            if (gk < DIN_) tma2d(sb + STG_A, &a0, gk, m0, full);
            else           tma2d(sb + STG_A, &a1, gk - DIN_, m0, full);
            tma2d(sb + STG_B, &b_m, gk, n0, full);
        }
        if (++s == NST) { s = 0; ph ^= 1; }
    }

    // write fp32 partial (n padded to 1024; each slot written exactly once)
    float* part = g_p2 + (size_t)blockIdx.z * MB_ * 1024;
    const int mrow = m0 + wm + (lane >> 2);
    const int ncol = n0 + wn + 2 * (lane & 3);

    #pragma unroll
    for (int mi = 0; mi < 4; mi++) {
        #pragma unroll
        for (int ni = 0; ni < 8; ni++) {
            const int n = ncol + ni * 8;
            const int ma = mrow + mi * 16;
            const int mb = ma + 8;
            float2 o0 = { acc[mi][ni][0], acc[mi][ni][1] };
            float2 o1 = { acc[mi][ni][2], acc[mi][ni][3] };
            *reinterpret_cast<float2*>(part + (size_t)ma * 1024 + n) = o0;
            *reinterpret_cast<float2*>(part + (size_t)mb * 1024 + n) = o1;
        }
    }
}

// reduce partials + bias -> out (float4 wide)
__global__ __launch_bounds__(256)
void reduce_k(const float* __restrict__ bias, float* __restrict__ outp)
{
    const size_t i = (size_t)blockIdx.x * blockDim.x + threadIdx.x;   // 4096*250
    if (i >= (size_t)MB_ * (ONN_ / 4)) return;
    const int m = (int)(i / (ONN_ / 4));
    const int n = 4 * (int)(i % (ONN_ / 4));
    const size_t off = (size_t)m * 1024 + n;
    float4 s = *reinterpret_cast<const float4*>(g_p2 + off);
    #pragma unroll
    for (int z = 1; z < KSPLIT; z++) {
        float4 v = *reinterpret_cast<const float4*>(g_p2 + (size_t)z * MB_ * 1024 + off);
        s.x += v.x; s.y += v.y; s.z += v.z; s.w += v.w;
    }
    const float4 bv = __ldg(reinterpret_cast<const float4*>(bias + n));
    s.x += bv.x; s.y += bv.y; s.z += bv.z; s.w += bv.w;
    *reinterpret_cast<float4*>(outp + (size_t)m * ONN_ + n) = s;
}

// ---------------- host side ---------------------
typedef CUresult (*PFN_tmap)(CUtensorMap*, CUtensorMapDataType, cuuint32_t, void*,
                             const cuuint64_t*, const cuuint64_t*, const cuuint32_t*,
                             const cuuint32_t*, CUtensorMapInterleave, CUtensorMapSwizzle,
                             CUtensorMapL2promotion, CUtensorMapFloatOOBfill);

static void mk2d(PFN_tmap f, CUtensorMap* m, void* p,
                 unsigned long long k, unsigned long long rows, unsigned box1)
{
    cuuint64_t dims[2] = { k, rows };
    cuuint64_t str[1]  = { k * 2 };
    cuuint32_t box[2]  = { 64u, box1 };
    cuuint32_t es[2]   = { 1u, 1u };
    f(m, CU_TENSOR_MAP_DATA_TYPE_FLOAT16, 2, p, dims, str, box, es,
      CU_TENSOR_MAP_INTERLEAVE_NONE, CU_TENSOR_MAP_SWIZZLE_128B,
      CU_TENSOR_MAP_L2_PROMOTION_L2_128B, CU_TENSOR_MAP_FLOAT_OOB_FILL_NONE);
}

extern "C" void kernel_launch(void* const* d_in, const int* in_sizes, int n_in,
                              void* d_out, int out_size)
{
    const float* x  = (const float*)d_in[0];
    const float* W1 = (const float*)d_in[1];
    const float* b1 = (const float*)d_in[2];
    const float* W2 = (const float*)d_in[3];
    const float* b2 = (const float*)d_in[4];
    float* out = (float*)d_out;

    void *xf, *w1f, *w2f, *h1;
    cudaGetSymbolAddress(&xf,  g_xf);
    cudaGetSymbolAddress(&w1f, g_w1f);
    cudaGetSymbolAddress(&w2f, g_w2f);
    cudaGetSymbolAddress(&h1,  g_h1);

    // merged fp32 -> fp16 conversion (one launch; 8 floats per thread)
    {
        const size_t total = N8X + N8W1 + N8W2;
        conv_all<<<(unsigned)((total + 255) / 256), 256>>>(x, W1, W2);
    }

    PFN_tmap enc = nullptr;
    cudaDriverEntryPointQueryResult qr;
    cudaGetDriverEntryPoint("cuTensorMapEncodeTiled", (void**)&enc,
                            cudaEnableDefault, &qr);

    CUtensorMap m_x128, m_h1128, m_w1_64, m_w2;
    mk2d(enc, &m_x128,  xf, DIN_, MB_,  128);
    mk2d(enc, &m_h1128, h1, HID_, MB_,  128);
    mk2d(enc, &m_w1_64, w1f, DIN_, HID_, 64);   // BN=64 tiles for GEMM1
    mk2d(enc, &m_w2,    w2f, K2_,  ONN_, 128);

    const int smem1 = STAGE0_OFF + 2 * 24576;   // 50176 -> 3 CTAs/SM
    const int smem2 = STAGE0_OFF + 2 * 32768;   // 66560 -> 2 CTAs/SM
    cudaFuncSetAttribute(gemm1_hmma, cudaFuncAttributeMaxDynamicSharedMemorySize, smem1);
    cudaFuncSetAttribute(gemm2_hmma, cudaFuncAttributeMaxDynamicSharedMemorySize, smem2);

    // GEMM1: h1 = relu(x @ W1^T + b1); 3 CTAs/SM, 12 warps/SM
    dim3 g1(MB_ / 128, HID_ / 64);    // (32, 256) = 8192 CTAs
    gemm1_hmma<<<g1, 128, smem1>>>(m_x128, m_w1_64, b1);

    // GEMM2: split-K partials, then reduce
    dim3 g2(MB_ / 128, 8, KSPLIT);    // (32, 8, 4) = 1024 CTAs
    gemm2_hmma<<<g2, 128, smem2>>>(m_x128, m_h1128, m_w2);

    const size_t nred = (size_t)MB_ * (ONN_ / 4);
    reduce_k<<<(unsigned)((nred + 255) / 256), 256>>>(b2, out);
}